// round 11
// baseline (speedup 1.0000x reference)
#include <cuda_runtime.h>
#include <cuda_fp16.h>

#define H     4096
#define K     32
#define WO    4065
#define SW    256            // output cols per strip
#define CW    288            // input cols per strip (SW + 32, 72 float4)
#define RCHK  226            // output rows per chunk
#define NSTR  16
#define NCHK  18
#define NT    512
#define BR    8              // input rows per batch
#define DPIT  296            // d pitch in floats (74 float4)
#define RPIT  296            // ring pitch in halves
#define SPIT  304            // S pitch in floats

// skew for stride-8 sliding-window reads: distinct banks for all 32 lanes
__device__ __forceinline__ int skS(int c) { return c + (c >> 5); }

__global__ void __launch_bounds__(NT, 2)
fused(const float* __restrict__ img,
      const float* __restrict__ som,
      const float* __restrict__ var,
      float* __restrict__ out)
{
    __shared__ float  simg[K * K];            //  4 KB
    __shared__ float4 d4[BR * (DPIT / 4)];    //  9.5 KB  dist batch (fp32)
    __shared__ __half ring[K * RPIT];         // 18.5 KB  last-32-rows dist (fp16)
    __shared__ float  S[BR * SPIT];           //  9.7 KB  vertical-sum snapshots

    const int tid = threadIdx.x;
    const int X0  = blockIdx.x * SW;
    const int J0  = blockIdx.y * RCHK;

    for (int i = tid; i < K * K; i += NT) simg[i] = img[i];
    __syncthreads();

    const int jMax  = min(J0 + RCHK - 1, WO - 1);
    const int yLast = min(jMax + K - 1, H - 1);
    const int nBat  = (yLast - J0 + BR) / BR;   // ceil((yLast-J0+1)/8)

    float* dS = (float*)d4;
    float  vsc = 0.f;                           // per-column vertical running sum
    const bool isCol = (tid < CW);

    for (int bb = 0; bb < nBat; bb++) {
        const int yb = J0 + bb * BR;

        // ---------- phase A: bulk loads + variance-weighted dist ----------
#pragma unroll
        for (int k = 0; k < 2; k++) {
            int idx = tid + k * NT;             // 576 slots: 8 rows x 72 float4
            if (idx < BR * 72) {
                int r  = idx / 72;
                int q  = idx - r * 72;
                int gy = yb + r;
                int gx = X0 + (q << 2);
                float4 dv = make_float4(0.f, 0.f, 0.f, 0.f);
                if (gy < H && gx < H) {
                    size_t o = ((size_t)gy << 12) + gx;
                    float4 s = *(const float4*)(som + o);
                    float4 v = *(const float4*)(var + o);
                    const float4 iv = ((const float4*)simg)[((gy & 31) << 3) + (q & 7)];
                    float f0 = iv.x - s.x, f1 = iv.y - s.y;
                    float f2 = iv.z - s.z, f3 = iv.w - s.w;
                    dv.x = __fdividef(f0 * f0, v.x + 1e-8f);
                    dv.y = __fdividef(f1 * f1, v.y + 1e-8f);
                    dv.z = __fdividef(f2 * f2, v.z + 1e-8f);
                    dv.w = __fdividef(f3 * f3, v.w + 1e-8f);
                }
                d4[r * (DPIT / 4) + q] = dv;
            }
        }
        __syncthreads();

        // ---------- phase B: vertical running sums (fp16 ring) ----------
        if (isCol) {
            const int c = tid;
#pragma unroll
            for (int r = 0; r < BR; r++) {
                const int y = yb + r;
                __half* rp = ring + (y & 31) * RPIT + c;
                if (y >= J0 + K) vsc -= __half2float(*rp);
                float dv = dS[r * DPIT + c];
                __half h = __float2half(dv);
                *rp = h;
                vsc += __half2float(h);         // round-tripped: exact cancel on pop
                S[r * SPIT + skS(c)] = vsc;
            }
        }
        __syncthreads();

        // ---------- phase C: horizontal 32-wide sliding windows ----------
        if (tid < 256) {
            const int r = tid >> 5;             // batch row
            const int u = tid & 31;             // 8-output group
            const int j = yb + r - (K - 1);     // output row
            if (j >= J0 && j <= jMax) {
                const float* Sr = S + r * SPIT;
                const int c0 = u << 3;
                float s = 0.f;
#pragma unroll
                for (int i = 0; i < K; i++) s += Sr[skS(c0 + i)];
                float* orow = out + (size_t)j * WO;
                int gx = X0 + c0;
                if (gx < WO) orow[gx] = s;
#pragma unroll
                for (int kk = 1; kk < 8; kk++) {
                    s += Sr[skS(c0 + kk + K - 1)] - Sr[skS(c0 + kk - 1)];
                    if (gx + kk < WO) orow[gx + kk] = s;
                }
            }
        }
        __syncthreads();   // protect d4 (phase A) and S (phase B) reuse
    }
}

extern "C" void kernel_launch(void* const* d_in, const int* in_sizes, int n_in,
                              void* d_out, int out_size)
{
    const float* img = (const float*)d_in[0];   // [32,32]
    const float* som = (const float*)d_in[1];   // [4096,4096]
    const float* var = (const float*)d_in[2];   // [4096,4096]
    float*       out = (float*)d_out;           // [4065,4065]

    dim3 grid(NSTR, NCHK);                      // 288 CTAs
    fused<<<grid, NT>>>(img, som, var, out);
}

// round 12
// speedup vs baseline: 1.4951x; 1.4951x over previous
#include <cuda_runtime.h>
#include <cuda_fp16.h>

#define H     4096
#define K     32
#define WO    4065
#define HP2   2048            // half2 pitch of scratch rows
#define RCH2  48              // output rows per consumer chunk
#define NXB   8               // x-blocks (256 half2 cols each)
#define NCHK2 85              // j-chunks
#define NCHUNK (NCHK2 * NXB)  // 680
#define N1    192             // producer CTAs
#define N2    104             // consumer CTAs
#define NCTA  (N1 + N2)       // 296 = 2/SM, fully resident

__device__ unsigned g_tmp[(size_t)H * HP2];   // fp16 scratch, 33.5 MB
__device__ int g_cnt[64];                     // per-64-row completion counters

__device__ __forceinline__ int sk(int x) { return x + (x >> 4); }
__device__ __forceinline__ int hs(int i) { return i + (i >> 3); }

__device__ __forceinline__ float4 ldcs4(const float4* p) {
    float4 r;
    asm volatile("ld.global.cs.v4.f32 {%0,%1,%2,%3}, [%4];"
                 : "=f"(r.x), "=f"(r.y), "=f"(r.z), "=f"(r.w) : "l"(p));
    return r;
}
__device__ __forceinline__ void stcs(float* p, float v) {
    asm volatile("st.global.cs.f32 [%0], %1;" :: "l"(p), "f"(v));
}
__device__ __forceinline__ float2 uph2(unsigned u) {
    return __half22float2(*(const __half2*)&u);
}

__global__ void reset_flags() { if (threadIdx.x < 64) g_cnt[threadIdx.x] = 0; }

__global__ void __launch_bounds__(256, 2)
fused_pc(const float* __restrict__ img,
         const float* __restrict__ som,
         const float* __restrict__ var,
         float* __restrict__ out)
{
    __shared__ float d[4352];
    __shared__ float irow[32];

    const int b = blockIdx.x;
    const int t = threadIdx.x;

    if (b < N1) {
        // ================= PRODUCER: horizontal pass, strided rows ==========
        for (int y = b; y < H; y += N1) {
            if (t < 32) irow[t] = img[((y & 31) << 5) + t];
            __syncthreads();

            const float4* s4 = (const float4*)(som + (size_t)y * H);
            const float4* v4 = (const float4*)(var + (size_t)y * H);
            const float4  iv = ((const float4*)irow)[t & 7];

#pragma unroll
            for (int k = 0; k < 4; k++) {
                int i4 = t + (k << 8);
                float4 s = ldcs4(s4 + i4);
                float4 v = ldcs4(v4 + i4);
                int x = i4 << 2;
                float f0 = iv.x - s.x, f1 = iv.y - s.y;
                float f2 = iv.z - s.z, f3 = iv.w - s.w;
                d[sk(x)]     = __fdividef(f0 * f0, v.x + 1e-8f);
                d[sk(x + 1)] = __fdividef(f1 * f1, v.y + 1e-8f);
                d[sk(x + 2)] = __fdividef(f2 * f2, v.z + 1e-8f);
                d[sk(x + 3)] = __fdividef(f3 * f3, v.w + 1e-8f);
            }
            __syncthreads();

            const int base = t << 4;
            const int jmax = (base < WO) ? min(16, WO - base) : 0;
            float res[16];
#pragma unroll
            for (int j = 0; j < 16; j++) res[j] = 0.f;

            if (jmax > 0) {
                float s = 0.f;
#pragma unroll
                for (int i = 0; i < K; i++) s += d[sk(base + i)];
                res[0] = s;
#pragma unroll
                for (int j = 1; j < 16; j++) {
                    s += d[sk(base + j + K - 1)] - d[sk(base + j - 1)];
                    if (j < jmax) res[j] = s;
                }
            }
            __syncthreads();

            unsigned* hbuf = (unsigned*)d;
#pragma unroll
            for (int p = 0; p < 8; p++) {
                __half2 h = __floats2half2_rn(res[2 * p], res[2 * p + 1]);
                hbuf[hs((t << 3) + p)] = *(unsigned*)&h;
            }
            __syncthreads();

            unsigned* grow = g_tmp + (size_t)y * HP2;
#pragma unroll
            for (int k = 0; k < 8; k++) {
                int idx = t + (k << 8);
                if (idx < 2033) grow[idx] = hbuf[hs(idx)];
            }

            __threadfence();            // each thread publishes its stores
            __syncthreads();
            if (t == 0) atomicAdd(&g_cnt[y >> 6], 1);
            // no trailing barrier needed: nothing reads irow/d until next sync
        }
    } else {
        // ================= CONSUMER: vertical pass, j-major chunks ==========
        for (int c = b - N1; c < NCHUNK; c += N2) {
            const int jc = c >> 3;                 // 0..84 (frontier order)
            const int xb = c & 7;
            const int j0 = jc * RCH2;
            const int n  = min(RCH2, WO - j0);
            const int gF = j0 >> 6;
            const int gL = (j0 + n + 30) >> 6;     // last input row needed

            if (t == 0) {
#pragma unroll 1
                for (int g = gF; g <= gL; g++)
                    while (*(volatile int*)&g_cnt[g] < 64) __nanosleep(128);
            }
            __syncthreads();
            __threadfence();                       // acquire-side ordering

            const int c2 = (xb << 8) + t;
            if (c2 < 2033) {
                const int x0 = c2 << 1;
                const bool x1ok = (x0 + 1) < WO;
                const unsigned* col = g_tmp + c2;

                float s0 = 0.f, s1 = 0.f;
                {
                    unsigned u[K];
#pragma unroll
                    for (int r = 0; r < K; r++)
                        u[r] = col[(size_t)(j0 + r) * HP2];
#pragma unroll
                    for (int r = 0; r < K; r++) {
                        float2 v = uph2(u[r]);
                        s0 += v.x; s1 += v.y;
                    }
                }
                {
                    float* o = out + (size_t)j0 * WO + x0;
                    stcs(o, s0);
                    if (x1ok) stcs(o + 1, s1);
                }

                for (int r = 1; r < n; r += 8) {
                    const int m = min(8, n - r);
                    unsigned ua[8], ub[8];
#pragma unroll
                    for (int i = 0; i < 8; i++) {
                        if (i < m) {
                            ua[i] = col[(size_t)(j0 + r + i + K - 1) * HP2];
                            ub[i] = col[(size_t)(j0 + r + i - 1) * HP2];
                        }
                    }
#pragma unroll
                    for (int i = 0; i < 8; i++) {
                        if (i < m) {
                            float2 a = uph2(ua[i]);
                            float2 bb = uph2(ub[i]);
                            s0 += a.x - bb.x;
                            s1 += a.y - bb.y;
                            float* o = out + (size_t)(j0 + r + i) * WO + x0;
                            stcs(o, s0);
                            if (x1ok) stcs(o + 1, s1);
                        }
                    }
                }
            }
            // no barrier needed between chunks (no shared state)
        }
    }
}

// ---------------------------------------------------------------------------
extern "C" void kernel_launch(void* const* d_in, const int* in_sizes, int n_in,
                              void* d_out, int out_size)
{
    const float* img = (const float*)d_in[0];   // [32,32]
    const float* som = (const float*)d_in[1];   // [4096,4096]
    const float* var = (const float*)d_in[2];   // [4096,4096]
    float*       out = (float*)d_out;           // [4065,4065]

    reset_flags<<<1, 64>>>();
    fused_pc<<<NCTA, 256>>>(img, som, var, out);
}

// round 13
// speedup vs baseline: 2.3891x; 1.5979x over previous
#include <cuda_runtime.h>
#include <cuda_fp16.h>

#define H     4096
#define K     32
#define WO    4065
#define HP2   2048            // half2 (uint) pitch of scratch rows
#define COUT  65              // outputs per pass-2 chunk (1 + 2*32)

// fp16 scratch: 4096 rows x 2048 half2 = 33.5 MB (L2-resident via .cs pass-1 loads)
__device__ unsigned g_tmp[(size_t)H * HP2];

__device__ __forceinline__ int sk(int x) { return x + (x >> 4); }
__device__ __forceinline__ int hs(int i) { return i + (i >> 3); }

__device__ __forceinline__ float4 ldcs4(const float4* p) {
    float4 r;
    asm volatile("ld.global.cs.v4.f32 {%0,%1,%2,%3}, [%4];"
                 : "=f"(r.x), "=f"(r.y), "=f"(r.z), "=f"(r.w) : "l"(p));
    return r;
}
__device__ __forceinline__ void stcs(float* p, float v) {
    asm volatile("st.global.cs.f32 [%0], %1;" :: "l"(p), "f"(v));
}

// ---------------------------------------------------------------------------
// Pass 1 (unchanged, near-roofline): dist + horizontal 32-wide box sum -> fp16
// ---------------------------------------------------------------------------
__global__ void __launch_bounds__(256, 8)
row_pass(const float* __restrict__ img,
         const float* __restrict__ som,
         const float* __restrict__ var)
{
    __shared__ float d[4352];
    __shared__ float irow[32];

    const int y = blockIdx.x;
    const int t = threadIdx.x;

    if (t < 32) irow[t] = img[((y & 31) << 5) + t];
    __syncthreads();

    const float4* s4 = (const float4*)(som + (size_t)y * H);
    const float4* v4 = (const float4*)(var + (size_t)y * H);
    const float4  iv = ((const float4*)irow)[t & 7];

#pragma unroll
    for (int k = 0; k < 4; k++) {
        int i4 = t + (k << 8);
        float4 s = ldcs4(s4 + i4);
        float4 v = ldcs4(v4 + i4);
        int x = i4 << 2;
        float f0 = iv.x - s.x, f1 = iv.y - s.y, f2 = iv.z - s.z, f3 = iv.w - s.w;
        d[sk(x)]     = __fdividef(f0 * f0, v.x + 1e-8f);
        d[sk(x + 1)] = __fdividef(f1 * f1, v.y + 1e-8f);
        d[sk(x + 2)] = __fdividef(f2 * f2, v.z + 1e-8f);
        d[sk(x + 3)] = __fdividef(f3 * f3, v.w + 1e-8f);
    }
    __syncthreads();

    const int base = t << 4;
    const int jmax = (base < WO) ? min(16, WO - base) : 0;
    float res[16];
#pragma unroll
    for (int j = 0; j < 16; j++) res[j] = 0.f;

    if (jmax > 0) {
        float s = 0.f;
#pragma unroll
        for (int i = 0; i < K; i++) s += d[sk(base + i)];
        res[0] = s;
#pragma unroll
        for (int j = 1; j < 16; j++) {
            s += d[sk(base + j + K - 1)] - d[sk(base + j - 1)];
            if (j < jmax) res[j] = s;
        }
    }
    __syncthreads();

    unsigned* hbuf = (unsigned*)d;
#pragma unroll
    for (int p = 0; p < 8; p++) {
        __half2 h = __floats2half2_rn(res[2 * p], res[2 * p + 1]);
        hbuf[hs((t << 3) + p)] = *(unsigned*)&h;
    }
    __syncthreads();

    unsigned* grow = g_tmp + (size_t)y * HP2;
#pragma unroll
    for (int k = 0; k < 8; k++) {
        int idx = t + (k << 8);
        if (idx < 2033) grow[idx] = hbuf[hs(idx)];
    }
}

// ---------------------------------------------------------------------------
// Pass 2: ONE column per thread. Warp = 32 consecutive columns:
//   stores: 1 full-efficiency wavefront/row; loads: even/odd lanes share a
//   scratch uint -> 64B/warp/row. Trailing subtract from a 32-deep fp32
//   register ring (ping-pong 32-row blocks, MLP=32).
// ---------------------------------------------------------------------------
__global__ void __launch_bounds__(256)
col_pass(float* __restrict__ out)
{
    const int x   = blockIdx.x * 256 + threadIdx.x;      // output column
    const int par = (x & 1) ? 16 : 0;                    // half select (bit shift)
    const unsigned* col = g_tmp + (x >> 1);
    const bool ok = x < WO;

    const int j0 = blockIdx.y * COUT;                    // 63 chunks

    unsigned u[32];
    float    pv[32];
    float    s = 0.f;

    // warmup rows j0 .. j0+31  (j0+31 <= 4061 < H)
#pragma unroll
    for (int i = 0; i < 32; i++)
        u[i] = col[(size_t)(j0 + i) * HP2];
#pragma unroll
    for (int i = 0; i < 32; i++) {
        float v = __half2float(__ushort_as_half((unsigned short)(u[i] >> par)));
        pv[i] = v;
        s += v;
    }
    if (ok) stcs(out + (size_t)j0 * WO + x, s);

#pragma unroll
    for (int blk = 0; blk < 2; blk++) {
        const int rbase = j0 + 32 + blk * 32;
        const int jb    = j0 + 1 + blk * 32;
#pragma unroll
        for (int i = 0; i < 32; i++) {
            int r = min(rbase + i, H - 1);               // clamp; clamped rows never output
            u[i] = col[(size_t)r * HP2];
        }
#pragma unroll
        for (int i = 0; i < 32; i++) {
            float v = __half2float(__ushort_as_half((unsigned short)(u[i] >> par)));
            s += v - pv[i];
            pv[i] = v;
            int j = jb + i;
            if (ok && j < WO) stcs(out + (size_t)j * WO + x, s);
        }
    }
}

// ---------------------------------------------------------------------------
extern "C" void kernel_launch(void* const* d_in, const int* in_sizes, int n_in,
                              void* d_out, int out_size)
{
    const float* img = (const float*)d_in[0];   // [32,32]
    const float* som = (const float*)d_in[1];   // [4096,4096]
    const float* var = (const float*)d_in[2];   // [4096,4096]
    float*       out = (float*)d_out;           // [4065,4065]

    row_pass<<<H, 256>>>(img, som, var);

    dim3 grid2(16,                              // 4096 cols / 256
               (WO + COUT - 1) / COUT);         // 63 -> 1008 CTAs
    col_pass<<<grid2, 256>>>(out);
}